// round 13
// baseline (speedup 1.0000x reference)
#include <cuda_runtime.h>
#include <cuda_fp16.h>
#include <cstdint>

namespace {
constexpr int Bc = 8, Sc = 1024, Dc = 64, BH = 128;
constexpr int TQ = 32, NT = 512;
constexpr int PH = 516;             // score row pitch in uint32 (half2) words
constexpr int SQ_P = 68;
constexpr int RP = 36;              // reduction slot row pitch (floats)
constexpr int SMEM_WORDS = TQ * PH + TQ * SQ_P;   // 18688 words = 74752 B
constexpr size_t ATTN_OFF = (size_t)BH * Sc * Dc;
}

// Scratch: fragment-packed fp16 K and V, bit-packed mask.
__device__ uint2    KF2[(size_t)BH * 16384];            // 16.7 MB
__device__ uint2    VF2[(size_t)BH * 16384];            // 16.7 MB
__device__ unsigned MBITS[(size_t)Bc * Sc * (Sc / 32)]; // 1 MB

__device__ __forceinline__ uint32_t h2u(__half2 h) {
    return *reinterpret_cast<uint32_t*>(&h);
}

__device__ __forceinline__ void mma16(float c[4],
                                      uint32_t a0, uint32_t a1,
                                      uint32_t a2, uint32_t a3,
                                      uint32_t b0, uint32_t b1) {
    asm volatile(
        "mma.sync.aligned.m16n8k16.row.col.f32.f16.f16.f32 "
        "{%0,%1,%2,%3}, {%4,%5,%6,%7}, {%8,%9}, {%0,%1,%2,%3};\n"
        : "+f"(c[0]), "+f"(c[1]), "+f"(c[2]), "+f"(c[3])
        : "r"(a0), "r"(a1), "r"(a2), "r"(a3), "r"(b0), "r"(b1));
}

// ---- pack K -> fp16 B-fragments: block (8n x 16k)
__global__ void pack_k_kernel(const float* __restrict__ K) {
    __shared__ __half h[64][72];
    int blk = blockIdx.x;                  // bh*16 + kt
    int tid = threadIdx.x;
    const float4* src = reinterpret_cast<const float4*>(K + (size_t)blk * 4096);
#pragma unroll
    for (int j = 0; j < 4; j++) {
        int i = tid + j * 256;
        int row = i >> 4, c4 = (i & 15) * 4;
        float4 v = src[i];
        h[row][c4 + 0] = __float2half_rn(v.x);
        h[row][c4 + 1] = __float2half_rn(v.y);
        h[row][c4 + 2] = __float2half_rn(v.z);
        h[row][c4 + 3] = __float2half_rn(v.w);
    }
    __syncthreads();
    uint2* dst = KF2 + (size_t)blk * 1024;
#pragma unroll
    for (int j = 0; j < 4; j++) {
        int o = tid + j * 256;
        int nb = o >> 7, rem = o & 127, ks = rem >> 5, l = rem & 31;
        int g = l >> 2, t = l & 3;
        int n = nb * 8 + g, k0 = ks * 16 + 2 * t;
        __half2 lo = __halves2half2(h[n][k0],     h[n][k0 + 1]);
        __half2 hi = __halves2half2(h[n][k0 + 8], h[n][k0 + 9]);
        dst[o] = make_uint2(h2u(lo), h2u(hi));
    }
}

// ---- pack V -> fp16 B-fragments: block (16k x 8d)
__global__ void pack_v_kernel(const float* __restrict__ V) {
    __shared__ __half h[64][72];           // row = k local, col = d
    int blk = blockIdx.x;                  // bh*16 + kc
    int tid = threadIdx.x;
    const float4* src = reinterpret_cast<const float4*>(V + (size_t)blk * 4096);
#pragma unroll
    for (int j = 0; j < 4; j++) {
        int i = tid + j * 256;
        int row = i >> 4, c4 = (i & 15) * 4;
        float4 v = src[i];
        h[row][c4 + 0] = __float2half_rn(v.x);
        h[row][c4 + 1] = __float2half_rn(v.y);
        h[row][c4 + 2] = __float2half_rn(v.z);
        h[row][c4 + 3] = __float2half_rn(v.w);
    }
    __syncthreads();
    uint2* dst = VF2 + (size_t)blk * 1024;
#pragma unroll
    for (int j = 0; j < 4; j++) {
        int o = tid + j * 256;
        int ksl = o >> 8, rem = o & 255, db = rem >> 5, l = rem & 31;
        int g = l >> 2, t = l & 3;
        int k0 = ksl * 16 + 2 * t, d = db * 8 + g;
        __half2 lo = __halves2half2(h[k0][d],     h[k0 + 1][d]);
        __half2 hi = __halves2half2(h[k0 + 8][d], h[k0 + 9][d]);
        dst[o] = make_uint2(h2u(lo), h2u(hi));
    }
}

// ---- mask -> bits
__global__ void mask_bits_kernel(const int* __restrict__ M) {
    size_t i = (size_t)blockIdx.x * 256 + threadIdx.x;
    unsigned bal = __ballot_sync(0xffffffffu, M[i] != 0);
    if ((threadIdx.x & 31) == 0) MBITS[i >> 5] = bal;
}

__global__ void __launch_bounds__(NT, 1)
attn_f16_kernel(const float* __restrict__ Qg_, float* __restrict__ out)
{
    extern __shared__ uint32_t smw[];
    uint32_t* sH = smw;                       // [32][PH] fp16 scores/attn
    float*    sQ = reinterpret_cast<float*>(smw + TQ * PH);  // [32][SQ_P]

    const int qt = blockIdx.x, bh = blockIdx.y, b = bh >> 4;
    const int tid = threadIdx.x, warp = tid >> 5, lane = tid & 31;
    const int gid = lane >> 2, tig = lane & 3;

    const float* Qg = Qg_ + ((size_t)bh * Sc + (size_t)qt * TQ) * Dc;
    float* outO = out + ((size_t)bh * Sc + (size_t)qt * TQ) * Dc;
    float* outA = out + ATTN_OFF + ((size_t)bh * Sc + (size_t)qt * TQ) * Sc;

    {   // Q tile (32x64) -> smem, *1/8
        float4 v = reinterpret_cast<const float4*>(Qg)[tid];
        int row = tid >> 4, c4 = tid & 15;
        float* dst = sQ + row * SQ_P + c4 * 4;
        dst[0] = v.x * 0.125f; dst[1] = v.y * 0.125f;
        dst[2] = v.z * 0.125f; dst[3] = v.w * 0.125f;
    }
    __syncthreads();

    // A fragments (Q/8) as fp16, both row-halves, 4 k16-steps
    uint32_t aq[2][4][4];
#pragma unroll
    for (int rh = 0; rh < 2; rh++)
#pragma unroll
        for (int ks = 0; ks < 4; ks++) {
            const float* p0 = sQ + (rh * 16 + gid) * SQ_P + ks * 16 + tig * 2;
            const float* p1 = p0 + 8 * SQ_P;
            float2 f0 = *reinterpret_cast<const float2*>(p0);
            float2 f1 = *reinterpret_cast<const float2*>(p1);
            float2 f2 = *reinterpret_cast<const float2*>(p0 + 8);
            float2 f3 = *reinterpret_cast<const float2*>(p1 + 8);
            aq[rh][ks][0] = h2u(__floats2half2_rn(f0.x, f0.y));
            aq[rh][ks][1] = h2u(__floats2half2_rn(f1.x, f1.y));
            aq[rh][ks][2] = h2u(__floats2half2_rn(f2.x, f2.y));
            aq[rh][ks][3] = h2u(__floats2half2_rn(f3.x, f3.y));
        }

    // ------ GEMM1: warp = (kp, wcb); kp owns tiles kt ≡ kp (mod 2), both rh --
    {
        const int kp = warp >> 3, wcb = warp & 7;
        const uint2* kf = KF2 + (size_t)bh * 16384 + kp * 1024
                          + wcb * 128 + lane;
        uint2 bf[2][4];
#pragma unroll
        for (int ks = 0; ks < 4; ks++)
            bf[0][ks] = __ldg(kf + ks * 32);
#pragma unroll
        for (int i = 0; i < 8; i++) {
            int cur = i & 1;
            if (i < 7) {
                const uint2* nx = kf + (size_t)(i + 1) * 2048;
#pragma unroll
                for (int ks = 0; ks < 4; ks++)
                    bf[cur ^ 1][ks] = __ldg(nx + ks * 32);
            }
            int kt = kp + 2 * i;
            int colw = kt * 32 + wcb * 4 + tig;    // half2-word column
#pragma unroll
            for (int rh = 0; rh < 2; rh++) {
                float cA[4] = {0,0,0,0}, cB[4] = {0,0,0,0};
                mma16(cA, aq[rh][0][0], aq[rh][0][1], aq[rh][0][2], aq[rh][0][3],
                      bf[cur][0].x, bf[cur][0].y);
                mma16(cB, aq[rh][1][0], aq[rh][1][1], aq[rh][1][2], aq[rh][1][3],
                      bf[cur][1].x, bf[cur][1].y);
                mma16(cA, aq[rh][2][0], aq[rh][2][1], aq[rh][2][2], aq[rh][2][3],
                      bf[cur][2].x, bf[cur][2].y);
                mma16(cB, aq[rh][3][0], aq[rh][3][1], aq[rh][3][2], aq[rh][3][3],
                      bf[cur][3].x, bf[cur][3].y);
                int w0 = (rh * 16 + gid) * PH + colw;
                sH[w0] = h2u(__floats2half2_rn(cA[0] + cB[0], cA[1] + cB[1]));
                sH[w0 + 8 * PH] =
                    h2u(__floats2half2_rn(cA[2] + cB[2], cA[3] + cB[3]));
            }
        }
    }
    __syncthreads();

    // ------ softmax + bitmask; fp32 attn -> gmem, fp16 attn/2 -> smem -------
#pragma unroll
    for (int rr = 0; rr < 2; rr++) {
        int row = warp * 2 + rr;
        uint4* srow4 = reinterpret_cast<uint4*>(sH + row * PH);
        unsigned mw = MBITS[((size_t)(b * Sc + qt * TQ + row)) * 32 + lane];

        float2 f[4][4];                       // 4 uint4 x 8 halves
        float mx = -3.0e38f;
#pragma unroll
        for (int i = 0; i < 4; i++) {
            uint4 q = srow4[lane + i * 32];
            f[i][0] = __half22float2(*reinterpret_cast<__half2*>(&q.x));
            f[i][1] = __half22float2(*reinterpret_cast<__half2*>(&q.y));
            f[i][2] = __half22float2(*reinterpret_cast<__half2*>(&q.z));
            f[i][3] = __half22float2(*reinterpret_cast<__half2*>(&q.w));
#pragma unroll
            for (int j = 0; j < 4; j++)
                mx = fmaxf(mx, fmaxf(f[i][j].x, f[i][j].y));
        }
#pragma unroll
        for (int o = 16; o > 0; o >>= 1)
            mx = fmaxf(mx, __shfl_xor_sync(0xffffffffu, mx, o));

        float sum = 0.f;
#pragma unroll
        for (int i = 0; i < 4; i++)
#pragma unroll
            for (int j = 0; j < 4; j++) {
                f[i][j].x = __expf(f[i][j].x - mx);
                f[i][j].y = __expf(f[i][j].y - mx);
                sum += f[i][j].x + f[i][j].y;
            }
#pragma unroll
        for (int o = 16; o > 0; o >>= 1)
            sum += __shfl_xor_sync(0xffffffffu, sum, o);
        float inv = 1.0f / sum;

        float4* arow = reinterpret_cast<float4*>(outA + (size_t)row * Sc);
#pragma unroll
        for (int i = 0; i < 4; i++) {
            int idx = lane + i * 32;               // uint4 index, 8 cols
            unsigned wd = __shfl_sync(0xffffffffu, mw, idx >> 2);
            unsigned mb = wd >> ((idx & 3) * 8);   // 8 mask bits
            float w0 = (mb & 1u)   ? f[i][0].x * inv : -100000.0f;
            float w1 = (mb & 2u)   ? f[i][0].y * inv : -100000.0f;
            float w2 = (mb & 4u)   ? f[i][1].x * inv : -100000.0f;
            float w3 = (mb & 8u)   ? f[i][1].y * inv : -100000.0f;
            float w4 = (mb & 16u)  ? f[i][2].x * inv : -100000.0f;
            float w5 = (mb & 32u)  ? f[i][2].y * inv : -100000.0f;
            float w6 = (mb & 64u)  ? f[i][3].x * inv : -100000.0f;
            float w7 = (mb & 128u) ? f[i][3].y * inv : -100000.0f;
            float4 o0 = make_float4(w0, w1, w2, w3);
            float4 o1 = make_float4(w4, w5, w6, w7);
            __stcs(&arow[idx * 2], o0);
            __stcs(&arow[idx * 2 + 1], o1);
            uint4 hh;
            hh.x = h2u(__floats2half2_rn(w0 * 0.5f, w1 * 0.5f));
            hh.y = h2u(__floats2half2_rn(w2 * 0.5f, w3 * 0.5f));
            hh.z = h2u(__floats2half2_rn(w4 * 0.5f, w5 * 0.5f));
            hh.w = h2u(__floats2half2_rn(w6 * 0.5f, w7 * 0.5f));
            srow4[idx] = hh;                       // fp16 attn/2
        }
    }
    __syncthreads();

    // ------ GEMM2: warp = (kq 0..7, dh 0..1); both row-halves ---------------
    const int kq = warp >> 1, dh = warp & 1;
    float c2[2][4][4];
#pragma unroll
    for (int rh = 0; rh < 2; rh++)
#pragma unroll
        for (int j = 0; j < 4; j++) {
            c2[rh][j][0] = 0.f; c2[rh][j][1] = 0.f;
            c2[rh][j][2] = 0.f; c2[rh][j][3] = 0.f;
        }
    {
        const uint2* vbase = VF2 + (size_t)bh * 16384
                             + (size_t)(kq * 8) * 256 + dh * 128 + lane;
        uint2 bv[2][4];
#pragma unroll
        for (int j = 0; j < 4; j++)
            bv[0][j] = __ldg(vbase + j * 32);
#pragma unroll
        for (int s = 0; s < 8; s++) {
            int cur = s & 1;
            if (s < 7) {
                const uint2* nx = vbase + (size_t)(s + 1) * 256;
#pragma unroll
                for (int j = 0; j < 4; j++)
                    bv[cur ^ 1][j] = __ldg(nx + j * 32);
            }
            int sg = kq * 8 + s;                   // global k16 step
            int wb = sg * 8 + tig;                 // half2 word in row
#pragma unroll
            for (int rh = 0; rh < 2; rh++) {
                int r0 = (rh * 16 + gid) * PH + wb;
                uint32_t a0 = sH[r0];
                uint32_t a1 = sH[r0 + 8 * PH];
                uint32_t a2 = sH[r0 + 4];
                uint32_t a3 = sH[r0 + 8 * PH + 4];
#pragma unroll
                for (int j = 0; j < 4; j++)
                    mma16(c2[rh][j], a0, a1, a2, a3,
                          bv[cur][j].x, bv[cur][j].y);
            }
        }
    }
    __syncthreads();      // all reads of sH fp16 attn done

    // ------ reduce kq partials (overlay on score buffer) --------------------
    float* sP = reinterpret_cast<float*>(sH);   // slots [14][32][RP]
    if (kq > 0) {
        float* base = sP + ((kq - 1) * 2 + dh) * (TQ * RP);
#pragma unroll
        for (int rh = 0; rh < 2; rh++)
#pragma unroll
            for (int j = 0; j < 4; j++) {
                int col = j * 8 + tig * 2;
                float* r0 = base + (rh * 16 + gid) * RP + col;
                *reinterpret_cast<float2*>(r0) =
                    make_float2(c2[rh][j][0], c2[rh][j][1]);
                *reinterpret_cast<float2*>(r0 + 8 * RP) =
                    make_float2(c2[rh][j][2], c2[rh][j][3]);
            }
    }
    __syncthreads();
    if (kq == 0) {
#pragma unroll
        for (int rh = 0; rh < 2; rh++)
#pragma unroll
            for (int j = 0; j < 4; j++) {
                int col = j * 8 + tig * 2;
                float2 a0 = make_float2(c2[rh][j][0], c2[rh][j][1]);
                float2 a1 = make_float2(c2[rh][j][2], c2[rh][j][3]);
#pragma unroll
                for (int p = 0; p < 7; p++) {
                    const float* base = sP + (p * 2 + dh) * (TQ * RP)
                                        + (rh * 16 + gid) * RP + col;
                    float2 o0 = *reinterpret_cast<const float2*>(base);
                    float2 o1 = *reinterpret_cast<const float2*>(base + 8 * RP);
                    a0.x += o0.x; a0.y += o0.y;
                    a1.x += o1.x; a1.y += o1.y;
                }
                int dcol = dh * 32 + col;
                *reinterpret_cast<float2*>(
                    outO + (rh * 16 + gid) * Dc + dcol) =
                    make_float2(a0.x * 2.f, a0.y * 2.f);
                *reinterpret_cast<float2*>(
                    outO + (rh * 16 + gid + 8) * Dc + dcol) =
                    make_float2(a1.x * 2.f, a1.y * 2.f);
            }
    }
}

extern "C" void kernel_launch(void* const* d_in, const int* in_sizes, int n_in,
                              void* d_out, int out_size)
{
    (void)in_sizes; (void)n_in; (void)out_size;
    const float* Q = (const float*)d_in[0];
    const float* K = (const float*)d_in[1];
    const float* V = (const float*)d_in[2];
    const int*   M = (const int*)d_in[3];
    float* out = (float*)d_out;

    pack_k_kernel<<<BH * 16, 256>>>(K);
    pack_v_kernel<<<BH * 16, 256>>>(V);
    mask_bits_kernel<<<(Bc * Sc * Sc) / 256, 256>>>(M);

    cudaFuncSetAttribute(attn_f16_kernel,
                         cudaFuncAttributeMaxDynamicSharedMemorySize,
                         SMEM_WORDS * (int)sizeof(uint32_t));
    dim3 grid(Sc / TQ, BH);
    attn_f16_kernel<<<grid, NT, SMEM_WORDS * sizeof(uint32_t)>>>(Q, out);
}

// round 14
// speedup vs baseline: 1.1497x; 1.1497x over previous
#include <cuda_runtime.h>
#include <cuda_fp16.h>
#include <cstdint>

namespace {
constexpr int Bc = 8, Sc = 1024, Dc = 64, BH = 128;
constexpr int TQ = 16, NT = 256;
constexpr int PH = 516;             // fp16-score row pitch in uint32 words
constexpr int SQ_P = 68;
constexpr int RP = 36;              // reduction slot row pitch (floats)
constexpr int SMEM_WORDS = TQ * PH + TQ * SQ_P;   // 9344 words = 37376 B
constexpr size_t ATTN_OFF = (size_t)BH * Sc * Dc;
}

// Scratch: fragment-packed fp16 K and V, bit-packed mask.
__device__ uint2    KF2[(size_t)BH * 16384];            // 16.7 MB
__device__ uint2    VF2[(size_t)BH * 16384];            // 16.7 MB
__device__ unsigned MBITS[(size_t)Bc * Sc * (Sc / 32)]; // 1 MB

__device__ __forceinline__ uint32_t h2u(__half2 h) {
    return *reinterpret_cast<uint32_t*>(&h);
}

__device__ __forceinline__ void mma16(float c[4],
                                      uint32_t a0, uint32_t a1,
                                      uint32_t a2, uint32_t a3,
                                      uint32_t b0, uint32_t b1) {
    asm volatile(
        "mma.sync.aligned.m16n8k16.row.col.f32.f16.f16.f32 "
        "{%0,%1,%2,%3}, {%4,%5,%6,%7}, {%8,%9}, {%0,%1,%2,%3};\n"
        : "+f"(c[0]), "+f"(c[1]), "+f"(c[2]), "+f"(c[3])
        : "r"(a0), "r"(a1), "r"(a2), "r"(a3), "r"(b0), "r"(b1));
}

// ---- pack K and V -> fp16 B-fragments (blockIdx.y: 0 = K, 1 = V)
__global__ void pack_kv_kernel(const float* __restrict__ K,
                               const float* __restrict__ V) {
    __shared__ __half h[64][72];
    int blk = blockIdx.x;                  // bh*16 + tile
    int kv  = blockIdx.y;
    int tid = threadIdx.x;
    const float* src_ = kv ? V : K;
    const float4* src = reinterpret_cast<const float4*>(src_ + (size_t)blk * 4096);
#pragma unroll
    for (int j = 0; j < 4; j++) {
        int i = tid + j * 256;
        int row = i >> 4, c4 = (i & 15) * 4;
        float4 v = src[i];
        h[row][c4 + 0] = __float2half_rn(v.x);
        h[row][c4 + 1] = __float2half_rn(v.y);
        h[row][c4 + 2] = __float2half_rn(v.z);
        h[row][c4 + 3] = __float2half_rn(v.w);
    }
    __syncthreads();
    if (kv == 0) {
        uint2* dst = KF2 + (size_t)blk * 1024;
#pragma unroll
        for (int j = 0; j < 4; j++) {
            int o = tid + j * 256;
            int nb = o >> 7, rem = o & 127, ks = rem >> 5, l = rem & 31;
            int g = l >> 2, t = l & 3;
            int n = nb * 8 + g, k0 = ks * 16 + 2 * t;
            __half2 lo = __halves2half2(h[n][k0],     h[n][k0 + 1]);
            __half2 hi = __halves2half2(h[n][k0 + 8], h[n][k0 + 9]);
            dst[o] = make_uint2(h2u(lo), h2u(hi));
        }
    } else {
        uint2* dst = VF2 + (size_t)blk * 1024;
#pragma unroll
        for (int j = 0; j < 4; j++) {
            int o = tid + j * 256;
            int ksl = o >> 8, rem = o & 255, db = rem >> 5, l = rem & 31;
            int g = l >> 2, t = l & 3;
            int k0 = ksl * 16 + 2 * t, d = db * 8 + g;
            __half2 lo = __halves2half2(h[k0][d],     h[k0 + 1][d]);
            __half2 hi = __halves2half2(h[k0 + 8][d], h[k0 + 9][d]);
            dst[o] = make_uint2(h2u(lo), h2u(hi));
        }
    }
}

// ---- mask -> bits
__global__ void mask_bits_kernel(const int* __restrict__ M) {
    size_t i = (size_t)blockIdx.x * 256 + threadIdx.x;
    unsigned bal = __ballot_sync(0xffffffffu, M[i] != 0);
    if ((threadIdx.x & 31) == 0) MBITS[i >> 5] = bal;
}

__global__ void __launch_bounds__(NT, 3)
attn_f16_kernel(const float* __restrict__ Qg_, float* __restrict__ out)
{
    extern __shared__ uint32_t smw[];
    uint32_t* sH = smw;                       // [16][PH] fp16 scores/attn
    float*    sQ = reinterpret_cast<float*>(smw + TQ * PH);  // [16][SQ_P]

    const int qt = blockIdx.x, bh = blockIdx.y, b = bh >> 4;
    const int tid = threadIdx.x, warp = tid >> 5, lane = tid & 31;
    const int gid = lane >> 2, tig = lane & 3;

    const float* Qg = Qg_ + ((size_t)bh * Sc + (size_t)qt * TQ) * Dc;
    float* outO = out + ((size_t)bh * Sc + (size_t)qt * TQ) * Dc;
    float* outA = out + ATTN_OFF + ((size_t)bh * Sc + (size_t)qt * TQ) * Sc;

    {   // Q tile -> smem, *1/8
        int row = tid >> 4, c4 = tid & 15;
        float4 v = reinterpret_cast<const float4*>(Qg)[tid];
        float* dst = sQ + row * SQ_P + c4 * 4;
        dst[0] = v.x * 0.125f; dst[1] = v.y * 0.125f;
        dst[2] = v.z * 0.125f; dst[3] = v.w * 0.125f;
    }
    __syncthreads();

    // A fragments (Q/8) as fp16, 4 k16-steps
    uint32_t aq[4][4];
#pragma unroll
    for (int ks = 0; ks < 4; ks++) {
        const float* p0 = sQ + gid * SQ_P + ks * 16 + tig * 2;
        const float* p1 = p0 + 8 * SQ_P;
        float2 f0 = *reinterpret_cast<const float2*>(p0);
        float2 f1 = *reinterpret_cast<const float2*>(p1);
        float2 f2 = *reinterpret_cast<const float2*>(p0 + 8);
        float2 f3 = *reinterpret_cast<const float2*>(p1 + 8);
        aq[ks][0] = h2u(__floats2half2_rn(f0.x, f0.y));
        aq[ks][1] = h2u(__floats2half2_rn(f1.x, f1.y));
        aq[ks][2] = h2u(__floats2half2_rn(f2.x, f2.y));
        aq[ks][3] = h2u(__floats2half2_rn(f3.x, f3.y));
    }

    // ---------------- GEMM1: scores = (Q/8) @ K^T -> fp16 smem ---------------
    {
        const uint2* kf = KF2 + (size_t)bh * 16384 + warp * 128 + lane;
        uint2 bf[2][4];
#pragma unroll
        for (int ks = 0; ks < 4; ks++)
            bf[0][ks] = __ldg(kf + ks * 32);

        for (int kt = 0; kt < 16; kt++) {
            int cur = kt & 1;
            if (kt < 15) {
                const uint2* nx = kf + (size_t)(kt + 1) * 1024;
#pragma unroll
                for (int ks = 0; ks < 4; ks++)
                    bf[cur ^ 1][ks] = __ldg(nx + ks * 32);
            }
            float cA[4] = {0,0,0,0}, cB[4] = {0,0,0,0};
            mma16(cA, aq[0][0], aq[0][1], aq[0][2], aq[0][3],
                  bf[cur][0].x, bf[cur][0].y);
            mma16(cB, aq[1][0], aq[1][1], aq[1][2], aq[1][3],
                  bf[cur][1].x, bf[cur][1].y);
            mma16(cA, aq[2][0], aq[2][1], aq[2][2], aq[2][3],
                  bf[cur][2].x, bf[cur][2].y);
            mma16(cB, aq[3][0], aq[3][1], aq[3][2], aq[3][3],
                  bf[cur][3].x, bf[cur][3].y);

            int wi = kt * 32 + warp * 4 + tig;    // half2 word column
            sH[gid * PH + wi] =
                h2u(__floats2half2_rn(cA[0] + cB[0], cA[1] + cB[1]));
            sH[(gid + 8) * PH + wi] =
                h2u(__floats2half2_rn(cA[2] + cB[2], cA[3] + cB[3]));
        }
    }
    __syncthreads();

    // ------- softmax + bitmask; fp32 attn -> gmem, fp16 attn/2 -> smem -------
#pragma unroll
    for (int rr = 0; rr < 2; rr++) {
        int row = warp * 2 + rr;
        uint4* srow4 = reinterpret_cast<uint4*>(sH + row * PH);
        unsigned mw = MBITS[((size_t)(b * Sc + qt * TQ + row)) * 32 + lane];

        float2 f[4][4];
        float mx = -3.0e38f;
#pragma unroll
        for (int i = 0; i < 4; i++) {
            uint4 q = srow4[lane + i * 32];
            f[i][0] = __half22float2(*reinterpret_cast<__half2*>(&q.x));
            f[i][1] = __half22float2(*reinterpret_cast<__half2*>(&q.y));
            f[i][2] = __half22float2(*reinterpret_cast<__half2*>(&q.z));
            f[i][3] = __half22float2(*reinterpret_cast<__half2*>(&q.w));
#pragma unroll
            for (int j = 0; j < 4; j++)
                mx = fmaxf(mx, fmaxf(f[i][j].x, f[i][j].y));
        }
#pragma unroll
        for (int o = 16; o > 0; o >>= 1)
            mx = fmaxf(mx, __shfl_xor_sync(0xffffffffu, mx, o));

        float sum = 0.f;
#pragma unroll
        for (int i = 0; i < 4; i++)
#pragma unroll
            for (int j = 0; j < 4; j++) {
                f[i][j].x = __expf(f[i][j].x - mx);
                f[i][j].y = __expf(f[i][j].y - mx);
                sum += f[i][j].x + f[i][j].y;
            }
#pragma unroll
        for (int o = 16; o > 0; o >>= 1)
            sum += __shfl_xor_sync(0xffffffffu, sum, o);
        float inv = 1.0f / sum;

        float4* arow = reinterpret_cast<float4*>(outA + (size_t)row * Sc);
#pragma unroll
        for (int i = 0; i < 4; i++) {
            int idx = lane + i * 32;               // uint4 index, 8 cols
            unsigned wd = __shfl_sync(0xffffffffu, mw, idx >> 2);
            unsigned mb = wd >> ((idx & 3) * 8);   // 8 mask bits
            float w0 = (mb & 1u)   ? f[i][0].x * inv : -100000.0f;
            float w1 = (mb & 2u)   ? f[i][0].y * inv : -100000.0f;
            float w2 = (mb & 4u)   ? f[i][1].x * inv : -100000.0f;
            float w3 = (mb & 8u)   ? f[i][1].y * inv : -100000.0f;
            float w4 = (mb & 16u)  ? f[i][2].x * inv : -100000.0f;
            float w5 = (mb & 32u)  ? f[i][2].y * inv : -100000.0f;
            float w6 = (mb & 64u)  ? f[i][3].x * inv : -100000.0f;
            float w7 = (mb & 128u) ? f[i][3].y * inv : -100000.0f;
            __stcs(&arow[idx * 2],     make_float4(w0, w1, w2, w3));
            __stcs(&arow[idx * 2 + 1], make_float4(w4, w5, w6, w7));
            uint4 hh;
            hh.x = h2u(__floats2half2_rn(w0 * 0.5f, w1 * 0.5f));
            hh.y = h2u(__floats2half2_rn(w2 * 0.5f, w3 * 0.5f));
            hh.z = h2u(__floats2half2_rn(w4 * 0.5f, w5 * 0.5f));
            hh.w = h2u(__floats2half2_rn(w6 * 0.5f, w7 * 0.5f));
            srow4[idx] = hh;                       // fp16 attn/2
        }
    }
    __syncthreads();

    // ------- GEMM2: 4-way k-split x 2-way d-split ---------------------------
    const int kq = warp >> 1, dh = warp & 1;
    float c2[4][4];
#pragma unroll
    for (int j = 0; j < 4; j++) {
        c2[j][0] = 0.f; c2[j][1] = 0.f; c2[j][2] = 0.f; c2[j][3] = 0.f;
    }
    {
        const uint2* vbase = VF2 + (size_t)bh * 16384
                             + (size_t)(kq * 16) * 256 + dh * 128 + lane;
        uint2 bv[2][4];
#pragma unroll
        for (int j = 0; j < 4; j++)
            bv[0][j] = __ldg(vbase + j * 32);
        for (int s = 0; s < 16; s++) {
            int cur = s & 1;
            if (s < 15) {
                const uint2* nx = vbase + (size_t)(s + 1) * 256;
#pragma unroll
                for (int j = 0; j < 4; j++)
                    bv[cur ^ 1][j] = __ldg(nx + j * 32);
            }
            int wb = (kq * 16 + s) * 8 + tig;      // half2 word in row
            int r0 = gid * PH + wb;
            uint32_t a0 = sH[r0];
            uint32_t a1 = sH[r0 + 8 * PH];
            uint32_t a2 = sH[r0 + 4];
            uint32_t a3 = sH[r0 + 8 * PH + 4];
#pragma unroll
            for (int j = 0; j < 4; j++)
                mma16(c2[j], a0, a1, a2, a3, bv[cur][j].x, bv[cur][j].y);
        }
    }
    __syncthreads();      // all reads of sH fp16 attn done

    // ---------------- reduce kq partials (overlay on sH) ---------------------
    float* sP = reinterpret_cast<float*>(sH);   // slots [6][16][RP]
    if (kq > 0) {
        float* base = sP + ((kq - 1) * 2 + dh) * (TQ * RP);
#pragma unroll
        for (int j = 0; j < 4; j++) {
            int col = j * 8 + tig * 2;
            *reinterpret_cast<float2*>(base + gid * RP + col) =
                make_float2(c2[j][0], c2[j][1]);
            *reinterpret_cast<float2*>(base + (gid + 8) * RP + col) =
                make_float2(c2[j][2], c2[j][3]);
        }
    }
    __syncthreads();
    if (kq == 0) {
#pragma unroll
        for (int j = 0; j < 4; j++) {
            int col = j * 8 + tig * 2;
            float2 a0 = make_float2(c2[j][0], c2[j][1]);
            float2 a1 = make_float2(c2[j][2], c2[j][3]);
#pragma unroll
            for (int p = 0; p < 3; p++) {
                const float* base = sP + (p * 2 + dh) * (TQ * RP);
                float2 o0 = *reinterpret_cast<const float2*>(base + gid * RP + col);
                float2 o1 = *reinterpret_cast<const float2*>(base + (gid + 8) * RP + col);
                a0.x += o0.x; a0.y += o0.y;
                a1.x += o1.x; a1.y += o1.y;
            }
            int dcol = dh * 32 + col;
            *reinterpret_cast<float2*>(outO + gid * Dc + dcol) =
                make_float2(a0.x * 2.f, a0.y * 2.f);
            *reinterpret_cast<float2*>(outO + (gid + 8) * Dc + dcol) =
                make_float2(a1.x * 2.f, a1.y * 2.f);
        }
    }
}

extern "C" void kernel_launch(void* const* d_in, const int* in_sizes, int n_in,
                              void* d_out, int out_size)
{
    (void)in_sizes; (void)n_in; (void)out_size;
    const float* Q = (const float*)d_in[0];
    const float* K = (const float*)d_in[1];
    const float* V = (const float*)d_in[2];
    const int*   M = (const int*)d_in[3];
    float* out = (float*)d_out;

    dim3 pg(BH * 16, 2);
    pack_kv_kernel<<<pg, 256>>>(K, V);
    mask_bits_kernel<<<(Bc * Sc * Sc) / 256, 256>>>(M);

    cudaFuncSetAttribute(attn_f16_kernel,
                         cudaFuncAttributeMaxDynamicSharedMemorySize,
                         SMEM_WORDS * (int)sizeof(uint32_t));
    dim3 grid(Sc / TQ, BH);
    attn_f16_kernel<<<grid, NT, SMEM_WORDS * sizeof(uint32_t)>>>(Q, out);
}

// round 15
// speedup vs baseline: 1.2353x; 1.0745x over previous
#include <cuda_runtime.h>
#include <cuda_fp16.h>
#include <cstdint>

namespace {
constexpr int Bc = 8, Sc = 1024, Dc = 64, BH = 128;
constexpr int TQ = 32, NT = 256;
constexpr int PH = 516;             // fp16-score row pitch in uint32 words
constexpr int SQ_P = 68;
constexpr int RP = 36;              // reduction slot row pitch (floats)
constexpr int SMEM_WORDS = TQ * PH + TQ * SQ_P;   // 18688 words = 74752 B
constexpr size_t ATTN_OFF = (size_t)BH * Sc * Dc;
}

// Scratch: fragment-packed fp16 K and V, bit-packed mask.
__device__ uint2    KF2[(size_t)BH * 16384];            // 16.7 MB
__device__ uint2    VF2[(size_t)BH * 16384];            // 16.7 MB
__device__ unsigned MBITS[(size_t)Bc * Sc * (Sc / 32)]; // 1 MB

__device__ __forceinline__ uint32_t h2u(__half2 h) {
    return *reinterpret_cast<uint32_t*>(&h);
}

__device__ __forceinline__ void mma16(float c[4],
                                      uint32_t a0, uint32_t a1,
                                      uint32_t a2, uint32_t a3,
                                      uint32_t b0, uint32_t b1) {
    asm volatile(
        "mma.sync.aligned.m16n8k16.row.col.f32.f16.f16.f32 "
        "{%0,%1,%2,%3}, {%4,%5,%6,%7}, {%8,%9}, {%0,%1,%2,%3};\n"
        : "+f"(c[0]), "+f"(c[1]), "+f"(c[2]), "+f"(c[3])
        : "r"(a0), "r"(a1), "r"(a2), "r"(a3), "r"(b0), "r"(b1));
}

// ---- pack K and V -> fp16 B-fragments (blockIdx.y: 0 = K, 1 = V)
__global__ void pack_kv_kernel(const float* __restrict__ K,
                               const float* __restrict__ V) {
    __shared__ __half h[64][72];
    int blk = blockIdx.x;                  // bh*16 + tile
    int kv  = blockIdx.y;
    int tid = threadIdx.x;
    const float* src_ = kv ? V : K;
    const float4* src = reinterpret_cast<const float4*>(src_ + (size_t)blk * 4096);
#pragma unroll
    for (int j = 0; j < 4; j++) {
        int i = tid + j * 256;
        int row = i >> 4, c4 = (i & 15) * 4;
        float4 v = src[i];
        h[row][c4 + 0] = __float2half_rn(v.x);
        h[row][c4 + 1] = __float2half_rn(v.y);
        h[row][c4 + 2] = __float2half_rn(v.z);
        h[row][c4 + 3] = __float2half_rn(v.w);
    }
    __syncthreads();
    if (kv == 0) {
        uint2* dst = KF2 + (size_t)blk * 1024;
#pragma unroll
        for (int j = 0; j < 4; j++) {
            int o = tid + j * 256;
            int nb = o >> 7, rem = o & 127, ks = rem >> 5, l = rem & 31;
            int g = l >> 2, t = l & 3;
            int n = nb * 8 + g, k0 = ks * 16 + 2 * t;
            __half2 lo = __halves2half2(h[n][k0],     h[n][k0 + 1]);
            __half2 hi = __halves2half2(h[n][k0 + 8], h[n][k0 + 9]);
            dst[o] = make_uint2(h2u(lo), h2u(hi));
        }
    } else {
        uint2* dst = VF2 + (size_t)blk * 1024;
#pragma unroll
        for (int j = 0; j < 4; j++) {
            int o = tid + j * 256;
            int ksl = o >> 8, rem = o & 255, db = rem >> 5, l = rem & 31;
            int g = l >> 2, t = l & 3;
            int k0 = ksl * 16 + 2 * t, d = db * 8 + g;
            __half2 lo = __halves2half2(h[k0][d],     h[k0 + 1][d]);
            __half2 hi = __halves2half2(h[k0 + 8][d], h[k0 + 9][d]);
            dst[o] = make_uint2(h2u(lo), h2u(hi));
        }
    }
}

// ---- mask -> bits
__global__ void mask_bits_kernel(const int* __restrict__ M) {
    size_t i = (size_t)blockIdx.x * 256 + threadIdx.x;
    unsigned bal = __ballot_sync(0xffffffffu, M[i] != 0);
    if ((threadIdx.x & 31) == 0) MBITS[i >> 5] = bal;
}

__global__ void __launch_bounds__(NT, 2)
attn_f16_kernel(const float* __restrict__ Qg_, float* __restrict__ out)
{
    extern __shared__ uint32_t smw[];
    uint32_t* sH = smw;                       // [32][PH] fp16 scores/attn
    float*    sQ = reinterpret_cast<float*>(smw + TQ * PH);  // [32][SQ_P]

    const int qt = blockIdx.x, bh = blockIdx.y, b = bh >> 4;
    const int tid = threadIdx.x, warp = tid >> 5, lane = tid & 31;
    const int gid = lane >> 2, tig = lane & 3;

    const float* Qg = Qg_ + ((size_t)bh * Sc + (size_t)qt * TQ) * Dc;
    float* outO = out + ((size_t)bh * Sc + (size_t)qt * TQ) * Dc;
    float* outA = out + ATTN_OFF + ((size_t)bh * Sc + (size_t)qt * TQ) * Sc;

    {   // Q tile (32x64) -> smem, *1/8  (2 float4 per thread)
#pragma unroll
        for (int j = 0; j < 2; j++) {
            int i = tid + j * 256;
            float4 v = reinterpret_cast<const float4*>(Qg)[i];
            int row = i >> 4, c4 = i & 15;
            float* dst = sQ + row * SQ_P + c4 * 4;
            dst[0] = v.x * 0.125f; dst[1] = v.y * 0.125f;
            dst[2] = v.z * 0.125f; dst[3] = v.w * 0.125f;
        }
    }
    __syncthreads();

    // A fragments (Q/8) as fp16, both row-halves, 4 k16-steps
    uint32_t aq[2][4][4];
#pragma unroll
    for (int rh = 0; rh < 2; rh++)
#pragma unroll
        for (int ks = 0; ks < 4; ks++) {
            const float* p0 = sQ + (rh * 16 + gid) * SQ_P + ks * 16 + tig * 2;
            const float* p1 = p0 + 8 * SQ_P;
            float2 f0 = *reinterpret_cast<const float2*>(p0);
            float2 f1 = *reinterpret_cast<const float2*>(p1);
            float2 f2 = *reinterpret_cast<const float2*>(p0 + 8);
            float2 f3 = *reinterpret_cast<const float2*>(p1 + 8);
            aq[rh][ks][0] = h2u(__floats2half2_rn(f0.x, f0.y));
            aq[rh][ks][1] = h2u(__floats2half2_rn(f1.x, f1.y));
            aq[rh][ks][2] = h2u(__floats2half2_rn(f2.x, f2.y));
            aq[rh][ks][3] = h2u(__floats2half2_rn(f3.x, f3.y));
        }

    // ------ GEMM1: warp owns 8-col block of every tile; both row halves ------
    {
        const uint2* kf = KF2 + (size_t)bh * 16384 + warp * 128 + lane;
        uint2 bf[2][4];
#pragma unroll
        for (int ks = 0; ks < 4; ks++)
            bf[0][ks] = __ldg(kf + ks * 32);

        for (int kt = 0; kt < 16; kt++) {
            int cur = kt & 1;
            if (kt < 15) {
                const uint2* nx = kf + (size_t)(kt + 1) * 1024;
#pragma unroll
                for (int ks = 0; ks < 4; ks++)
                    bf[cur ^ 1][ks] = __ldg(nx + ks * 32);
            }
            int wi = kt * 32 + warp * 4 + tig;    // half2 word column
#pragma unroll
            for (int rh = 0; rh < 2; rh++) {
                float cA[4] = {0,0,0,0}, cB[4] = {0,0,0,0};
                mma16(cA, aq[rh][0][0], aq[rh][0][1], aq[rh][0][2], aq[rh][0][3],
                      bf[cur][0].x, bf[cur][0].y);
                mma16(cB, aq[rh][1][0], aq[rh][1][1], aq[rh][1][2], aq[rh][1][3],
                      bf[cur][1].x, bf[cur][1].y);
                mma16(cA, aq[rh][2][0], aq[rh][2][1], aq[rh][2][2], aq[rh][2][3],
                      bf[cur][2].x, bf[cur][2].y);
                mma16(cB, aq[rh][3][0], aq[rh][3][1], aq[rh][3][2], aq[rh][3][3],
                      bf[cur][3].x, bf[cur][3].y);
                int w0 = (rh * 16 + gid) * PH + wi;
                sH[w0] = h2u(__floats2half2_rn(cA[0] + cB[0], cA[1] + cB[1]));
                sH[w0 + 8 * PH] =
                    h2u(__floats2half2_rn(cA[2] + cB[2], cA[3] + cB[3]));
            }
        }
    }
    __syncthreads();

    // ------ softmax + bitmask; fp32 attn -> gmem, fp16 attn/2 -> smem -------
#pragma unroll
    for (int rr = 0; rr < 4; rr++) {          // each warp owns 4 rows
        int row = warp * 4 + rr;
        uint4* srow4 = reinterpret_cast<uint4*>(sH + row * PH);
        unsigned mw = MBITS[((size_t)(b * Sc + qt * TQ + row)) * 32 + lane];

        float2 f[4][4];
        float mx = -3.0e38f;
#pragma unroll
        for (int i = 0; i < 4; i++) {
            uint4 q = srow4[lane + i * 32];
            f[i][0] = __half22float2(*reinterpret_cast<__half2*>(&q.x));
            f[i][1] = __half22float2(*reinterpret_cast<__half2*>(&q.y));
            f[i][2] = __half22float2(*reinterpret_cast<__half2*>(&q.z));
            f[i][3] = __half22float2(*reinterpret_cast<__half2*>(&q.w));
#pragma unroll
            for (int j = 0; j < 4; j++)
                mx = fmaxf(mx, fmaxf(f[i][j].x, f[i][j].y));
        }
#pragma unroll
        for (int o = 16; o > 0; o >>= 1)
            mx = fmaxf(mx, __shfl_xor_sync(0xffffffffu, mx, o));

        float sum = 0.f;
#pragma unroll
        for (int i = 0; i < 4; i++)
#pragma unroll
            for (int j = 0; j < 4; j++) {
                f[i][j].x = __expf(f[i][j].x - mx);
                f[i][j].y = __expf(f[i][j].y - mx);
                sum += f[i][j].x + f[i][j].y;
            }
#pragma unroll
        for (int o = 16; o > 0; o >>= 1)
            sum += __shfl_xor_sync(0xffffffffu, sum, o);
        float inv = 1.0f / sum;

        float4* arow = reinterpret_cast<float4*>(outA + (size_t)row * Sc);
#pragma unroll
        for (int i = 0; i < 4; i++) {
            int idx = lane + i * 32;               // uint4 index, 8 cols
            unsigned wd = __shfl_sync(0xffffffffu, mw, idx >> 2);
            unsigned mb = wd >> ((idx & 3) * 8);   // 8 mask bits
            float w0 = (mb & 1u)   ? f[i][0].x * inv : -100000.0f;
            float w1 = (mb & 2u)   ? f[i][0].y * inv : -100000.0f;
            float w2 = (mb & 4u)   ? f[i][1].x * inv : -100000.0f;
            float w3 = (mb & 8u)   ? f[i][1].y * inv : -100000.0f;
            float w4 = (mb & 16u)  ? f[i][2].x * inv : -100000.0f;
            float w5 = (mb & 32u)  ? f[i][2].y * inv : -100000.0f;
            float w6 = (mb & 64u)  ? f[i][3].x * inv : -100000.0f;
            float w7 = (mb & 128u) ? f[i][3].y * inv : -100000.0f;
            __stcs(&arow[idx * 2],     make_float4(w0, w1, w2, w3));
            __stcs(&arow[idx * 2 + 1], make_float4(w4, w5, w6, w7));
            uint4 hh;
            hh.x = h2u(__floats2half2_rn(w0 * 0.5f, w1 * 0.5f));
            hh.y = h2u(__floats2half2_rn(w2 * 0.5f, w3 * 0.5f));
            hh.z = h2u(__floats2half2_rn(w4 * 0.5f, w5 * 0.5f));
            hh.w = h2u(__floats2half2_rn(w6 * 0.5f, w7 * 0.5f));
            srow4[idx] = hh;                       // fp16 attn/2
        }
    }
    __syncthreads();

    // ------ GEMM2: 4-way k-split x 2-way d-split; both row halves -----------
    const int kq = warp >> 1, dh = warp & 1;
    float c2[2][4][4];
#pragma unroll
    for (int rh = 0; rh < 2; rh++)
#pragma unroll
        for (int j = 0; j < 4; j++) {
            c2[rh][j][0] = 0.f; c2[rh][j][1] = 0.f;
            c2[rh][j][2] = 0.f; c2[rh][j][3] = 0.f;
        }
    {
        const uint2* vbase = VF2 + (size_t)bh * 16384
                             + (size_t)(kq * 16) * 256 + dh * 128 + lane;
        uint2 bv[2][4];
#pragma unroll
        for (int j = 0; j < 4; j++)
            bv[0][j] = __ldg(vbase + j * 32);
        for (int s = 0; s < 16; s++) {
            int cur = s & 1;
            if (s < 15) {
                const uint2* nx = vbase + (size_t)(s + 1) * 256;
#pragma unroll
                for (int j = 0; j < 4; j++)
                    bv[cur ^ 1][j] = __ldg(nx + j * 32);
            }
            int wb = (kq * 16 + s) * 8 + tig;      // half2 word in row
#pragma unroll
            for (int rh = 0; rh < 2; rh++) {
                int r0 = (rh * 16 + gid) * PH + wb;
                uint32_t a0 = sH[r0];
                uint32_t a1 = sH[r0 + 8 * PH];
                uint32_t a2 = sH[r0 + 4];
                uint32_t a3 = sH[r0 + 8 * PH + 4];
#pragma unroll
                for (int j = 0; j < 4; j++)
                    mma16(c2[rh][j], a0, a1, a2, a3,
                          bv[cur][j].x, bv[cur][j].y);
            }
        }
    }
    __syncthreads();      // all reads of sH fp16 attn done

    // ---------------- reduce kq partials (overlay on sH) ---------------------
    float* sP = reinterpret_cast<float*>(sH);   // slots [6][32][RP]
    if (kq > 0) {
        float* base = sP + ((kq - 1) * 2 + dh) * (TQ * RP);
#pragma unroll
        for (int rh = 0; rh < 2; rh++)
#pragma unroll
            for (int j = 0; j < 4; j++) {
                int col = j * 8 + tig * 2;
                float* r0 = base + (rh * 16 + gid) * RP + col;
                *reinterpret_cast<float2*>(r0) =
                    make_float2(c2[rh][j][0], c2[rh][j][1]);
                *reinterpret_cast<float2*>(r0 + 8 * RP) =
                    make_float2(c2[rh][j][2], c2[rh][j][3]);
            }
    }
    __syncthreads();
    if (kq == 0) {
#pragma unroll
        for (int rh = 0; rh < 2; rh++)
#pragma unroll
            for (int j = 0; j < 4; j++) {
                int col = j * 8 + tig * 2;
                float2 a0 = make_float2(c2[rh][j][0], c2[rh][j][1]);
                float2 a1 = make_float2(c2[rh][j][2], c2[rh][j][3]);
#pragma unroll
                for (int p = 0; p < 3; p++) {
                    const float* base = sP + (p * 2 + dh) * (TQ * RP)
                                        + (rh * 16 + gid) * RP + col;
                    float2 o0 = *reinterpret_cast<const float2*>(base);
                    float2 o1 = *reinterpret_cast<const float2*>(base + 8 * RP);
                    a0.x += o0.x; a0.y += o0.y;
                    a1.x += o1.x; a1.y += o1.y;
                }
                int dcol = dh * 32 + col;
                *reinterpret_cast<float2*>(
                    outO + (rh * 16 + gid) * Dc + dcol) =
                    make_float2(a0.x * 2.f, a0.y * 2.f);
                *reinterpret_cast<float2*>(
                    outO + (rh * 16 + gid + 8) * Dc + dcol) =
                    make_float2(a1.x * 2.f, a1.y * 2.f);
            }
    }
}

extern "C" void kernel_launch(void* const* d_in, const int* in_sizes, int n_in,
                              void* d_out, int out_size)
{
    (void)in_sizes; (void)n_in; (void)out_size;
    const float* Q = (const float*)d_in[0];
    const float* K = (const float*)d_in[1];
    const float* V = (const float*)d_in[2];
    const int*   M = (const int*)d_in[3];
    float* out = (float*)d_out;

    dim3 pg(BH * 16, 2);
    pack_kv_kernel<<<pg, 256>>>(K, V);
    mask_bits_kernel<<<(Bc * Sc * Sc) / 256, 256>>>(M);

    cudaFuncSetAttribute(attn_f16_kernel,
                         cudaFuncAttributeMaxDynamicSharedMemorySize,
                         SMEM_WORDS * (int)sizeof(uint32_t));
    dim3 grid(Sc / TQ, BH);
    attn_f16_kernel<<<grid, NT, SMEM_WORDS * sizeof(uint32_t)>>>(Q, out);
}